// round 3
// baseline (speedup 1.0000x reference)
#include <cuda_runtime.h>

// ---------------------------------------------------------------------------
// BaseAttention fused kernel (fp32, CUDA-core baseline)
//
// Math (per batch row b):
//   att  = obs[b, 32:544]  -> 32 objs x 16 (15 feats + mask)
//   h1   = relu(W1 @ f + b1); h2 = relu(W2 @ h1 + b2); h3 = W3 @ h2 + b3
//   xr   = h3 * mask
//   query= sum_o xr / (sum mask + 1e-5)
//   p    = (Ur^T Uq) query            (M precomputed once per launch)
//   logit[o] = p . xr[o] + (1-mask[o]) * -1e9
//   w    = softmax(logit); out_att = sum_o w[o] xr[o]
//   out  = [obs[b,:32], obs[b,544:576], out_att]
// ---------------------------------------------------------------------------

#define kSMs   148
#define kBatch 32768
#define kObs   576
#define kD     128
#define kObj   32
#define kOutC  192
#define kPad   132                     // padded row (floats) for conflict-free LDS.128

#define W_FLOATS    (kD * kPad)                                    // 16896
#define HALF_FLOATS (512 + 2 * kObj * kPad + 2 * kD + 2 * kObj)    // 9280
#define SMEM_FLOATS (2 * W_FLOATS + 2 * HALF_FLOATS)               // 52352
#define SMEM_BYTES  (SMEM_FLOATS * sizeof(float))                  // 209408 B

__device__ float g_MT[kD * kD];   // MT[j*128 + t] = sum_k Ur[k,t] * Uq[k,j]

// M = Ur^T Uq, stored so the main kernel's read (fixed j, threads over t) is coalesced.
__global__ void precompute_MT(const float* __restrict__ Uq, const float* __restrict__ Ur) {
    int j = blockIdx.x;      // 0..127
    int t = threadIdx.x;     // 0..127
    float acc = 0.f;
    #pragma unroll 8
    for (int k = 0; k < kD; ++k)
        acc += Ur[k * kD + t] * Uq[k * kD + j];
    g_MT[j * kD + t] = acc;
}

__device__ __forceinline__ void half_bar(int half) {
    asm volatile("bar.sync %0, %1;" :: "r"(half + 1), "r"(128) : "memory");
}

extern __shared__ float smem[];

__global__ __launch_bounds__(256, 1) void fused_attn_kernel(
    const float* __restrict__ obs,
    const float* __restrict__ W1, const float* __restrict__ b1,
    const float* __restrict__ W2, const float* __restrict__ b2,
    const float* __restrict__ W3, const float* __restrict__ b3,
    float* __restrict__ out)
{
    const int tid  = threadIdx.x;
    const int half = tid >> 7;     // 0 or 1: which batch row of the pair
    const int t    = tid & 127;    // output-dim lane, 0..127

    float* W2q = smem;                          // [128][132]
    float* W3q = smem + W_FLOATS;               // [128][132]
    float* hb  = smem + 2 * W_FLOATS + half * HALF_FLOATS;
    float* fs      = hb;                        // 512: raw att (32 objs x 16)
    float* bufA    = hb + 512;                  // [32][132]
    float* bufB    = bufA + kObj * kPad;        // [32][132]
    float* query_s = bufB + kObj * kPad;        // 128
    float* p_s     = query_s + kD;              // 128
    float* logit_s = p_s + kD;                  // 32
    float* w_s     = logit_s + kObj;            // 32

    // ---- stage W2 / W3 into padded smem (coalesced float4) ----
    for (int i = tid; i < (kD * kD) / 4; i += 256) {
        int r = i >> 5, c4 = i & 31;
        *(float4*)(W2q + r * kPad + c4 * 4) = ((const float4*)W2)[i];
        *(float4*)(W3q + r * kPad + c4 * 4) = ((const float4*)W3)[i];
    }
    // ---- per-thread W1 row + biases in registers ----
    float w1r[15];
    #pragma unroll
    for (int f = 0; f < 15; ++f) w1r[f] = W1[t * 15 + f];
    const float b1r = b1[t], b2r = b2[t], b3r = b3[t];
    __syncthreads();

    for (int pair = blockIdx.x; pair < kBatch / 2; pair += kSMs) {
        const int b = pair * 2 + half;
        const float*  orow   = obs + (size_t)b * kObs;
        float*        outrow = out + (size_t)b * kOutC;

        // ---- load att (512 floats) into fs; write aux passthrough ----
        *(float4*)(fs + 4 * t) = ((const float4*)(orow + 32))[t];
        if (t < 16) {
            float4 v = (t < 8) ? ((const float4*)orow)[t]
                               : ((const float4*)orow)[136 + (t - 8)];
            ((float4*)outrow)[t] = v;
        }
        half_bar(half);

        // ---- mask sum (all threads redundantly; broadcast LDS) ----
        float msum = 0.f;
        #pragma unroll
        for (int o = 0; o < kObj; ++o) msum += fs[o * 16 + 15];

        // ---- layer 1: h1[o][t] = relu(W1[t,:].f[o,:] + b1[t]) ----
        for (int o = 0; o < kObj; ++o) {
            const float4 f0 = *(const float4*)(fs + o * 16);
            const float4 f1 = *(const float4*)(fs + o * 16 + 4);
            const float4 f2 = *(const float4*)(fs + o * 16 + 8);
            const float4 f3 = *(const float4*)(fs + o * 16 + 12);
            float a = b1r;
            a += w1r[0] * f0.x + w1r[1] * f0.y + w1r[2]  * f0.z + w1r[3]  * f0.w;
            a += w1r[4] * f1.x + w1r[5] * f1.y + w1r[6]  * f1.z + w1r[7]  * f1.w;
            a += w1r[8] * f2.x + w1r[9] * f2.y + w1r[10] * f2.z + w1r[11] * f2.w;
            a += w1r[12] * f3.x + w1r[13] * f3.y + w1r[14] * f3.z;   // f3.w = mask, skipped
            bufA[o * kPad + t] = fmaxf(a, 0.f);
        }
        half_bar(half);

        // ---- layer 2: bufB = relu(W2 @ bufA + b2), 8-obj x 4-e blocking ----
        {
            const float* wrow = W2q + t * kPad;
            for (int g = 0; g < 4; ++g) {
                float acc[8];
                #pragma unroll
                for (int i = 0; i < 8; ++i) acc[i] = b2r;
                const float* hbase = bufA + g * 8 * kPad;
                #pragma unroll 8
                for (int e4 = 0; e4 < 32; ++e4) {
                    const float4 w = *(const float4*)(wrow + 4 * e4);
                    #pragma unroll
                    for (int o8 = 0; o8 < 8; ++o8) {
                        const float4 h = *(const float4*)(hbase + o8 * kPad + 4 * e4);
                        acc[o8] += w.x * h.x + w.y * h.y + w.z * h.z + w.w * h.w;
                    }
                }
                #pragma unroll
                for (int o8 = 0; o8 < 8; ++o8)
                    bufB[(g * 8 + o8) * kPad + t] = fmaxf(acc[o8], 0.f);
            }
        }
        half_bar(half);

        // ---- layer 3 + mask + query accumulation: bufA = xr ----
        float qsum = 0.f;
        {
            const float* wrow = W3q + t * kPad;
            for (int g = 0; g < 4; ++g) {
                float acc[8];
                #pragma unroll
                for (int i = 0; i < 8; ++i) acc[i] = b3r;
                const float* hbase = bufB + g * 8 * kPad;
                #pragma unroll 8
                for (int e4 = 0; e4 < 32; ++e4) {
                    const float4 w = *(const float4*)(wrow + 4 * e4);
                    #pragma unroll
                    for (int o8 = 0; o8 < 8; ++o8) {
                        const float4 h = *(const float4*)(hbase + o8 * kPad + 4 * e4);
                        acc[o8] += w.x * h.x + w.y * h.y + w.z * h.z + w.w * h.w;
                    }
                }
                #pragma unroll
                for (int o8 = 0; o8 < 8; ++o8) {
                    const int o = g * 8 + o8;
                    const float xr = acc[o8] * fs[o * 16 + 15];
                    bufA[o * kPad + t] = xr;
                    qsum += xr;
                }
            }
        }
        query_s[t] = qsum / (msum + 1e-5f);
        half_bar(half);

        // ---- p = M query  (M resident in L2) ----
        float p = 0.f;
        #pragma unroll 8
        for (int j = 0; j < kD; ++j)
            p += g_MT[j * kD + t] * query_s[j];
        p_s[t] = p;
        half_bar(half);

        // ---- logits: 4 threads per object, conflict-free smem pattern ----
        {
            const int o = t >> 2, c = t & 3;
            float ls = 0.f;
            #pragma unroll 8
            for (int k = 0; k < 32; ++k)
                ls += p_s[c + 4 * k] * bufA[o * kPad + c + 4 * k];
            ls += __shfl_xor_sync(0xffffffffu, ls, 1);
            ls += __shfl_xor_sync(0xffffffffu, ls, 2);
            if (c == 0)
                logit_s[o] = ls + (1.f - fs[o * 16 + 15]) * -1e9f;
        }
        half_bar(half);

        // ---- softmax over 32 objects (warp 0 of this half) ----
        if (t < 32) {
            const float l = logit_s[t];
            float mx = l;
            #pragma unroll
            for (int s = 16; s > 0; s >>= 1)
                mx = fmaxf(mx, __shfl_xor_sync(0xffffffffu, mx, s));
            const float e = __expf(l - mx);
            float ssum = e;
            #pragma unroll
            for (int s = 16; s > 0; s >>= 1)
                ssum += __shfl_xor_sync(0xffffffffu, ssum, s);
            w_s[t] = e / ssum;
        }
        half_bar(half);

        // ---- out_att = sum_o w[o] * xr[o] ----
        float oacc = 0.f;
        #pragma unroll 8
        for (int o = 0; o < kObj; ++o)
            oacc += w_s[o] * bufA[o * kPad + t];
        outrow[64 + t] = oacc;

        half_bar(half);   // protect fs/bufA before next iteration's overwrite
    }
}

extern "C" void kernel_launch(void* const* d_in, const int* in_sizes, int n_in,
                              void* d_out, int out_size) {
    const float* obs = (const float*)d_in[0];
    const float* W1  = (const float*)d_in[1];
    const float* b1  = (const float*)d_in[2];
    const float* W2  = (const float*)d_in[3];
    const float* b2  = (const float*)d_in[4];
    const float* W3  = (const float*)d_in[5];
    const float* b3  = (const float*)d_in[6];
    const float* Uq  = (const float*)d_in[7];
    const float* Ur  = (const float*)d_in[8];
    float* out = (float*)d_out;

    cudaFuncSetAttribute(fused_attn_kernel,
                         cudaFuncAttributeMaxDynamicSharedMemorySize,
                         (int)SMEM_BYTES);

    precompute_MT<<<kD, kD>>>(Uq, Ur);
    fused_attn_kernel<<<kSMs, 256, SMEM_BYTES>>>(obs, W1, b1, W2, b2, W3, b3, out);
}

// round 4
// speedup vs baseline: 1.0013x; 1.0013x over previous
#include <cuda_runtime.h>

// ---------------------------------------------------------------------------
// BaseAttention fused kernel (fp32, CUDA-core baseline)
//
// Math (per batch row b):
//   att  = obs[b, 32:544]  -> 32 objs x 16 (15 feats + mask)
//   h1   = relu(W1 @ f + b1); h2 = relu(W2 @ h1 + b2); h3 = W3 @ h2 + b3
//   xr   = h3 * mask
//   query= sum_o xr / (sum mask + 1e-5)
//   p    = (Ur^T Uq) query            (M precomputed once per launch)
//   logit[o] = p . xr[o] + (1-mask[o]) * -1e9
//   w    = softmax(logit); out_att = sum_o w[o] xr[o]
//   out  = [obs[b,:32], obs[b,544:576], out_att]
// ---------------------------------------------------------------------------

#define kSMs   148
#define kBatch 32768
#define kObs   576
#define kD     128
#define kObj   32
#define kOutC  192
#define kPad   132                     // padded row (floats) for conflict-free LDS.128

#define W_FLOATS    (kD * kPad)                                    // 16896
#define HALF_FLOATS (512 + 2 * kObj * kPad + 2 * kD + 2 * kObj)    // 9280
#define SMEM_FLOATS (2 * W_FLOATS + 2 * HALF_FLOATS)               // 52352
#define SMEM_BYTES  (SMEM_FLOATS * sizeof(float))                  // 209408 B

__device__ float g_MT[kD * kD];   // MT[j*128 + t] = sum_k Ur[k,t] * Uq[k,j]

// M = Ur^T Uq, stored so the main kernel's read (fixed j, threads over t) is coalesced.
__global__ void precompute_MT(const float* __restrict__ Uq, const float* __restrict__ Ur) {
    int j = blockIdx.x;      // 0..127
    int t = threadIdx.x;     // 0..127
    float acc = 0.f;
    #pragma unroll 8
    for (int k = 0; k < kD; ++k)
        acc += Ur[k * kD + t] * Uq[k * kD + j];
    g_MT[j * kD + t] = acc;
}

__device__ __forceinline__ void half_bar(int half) {
    asm volatile("bar.sync %0, %1;" :: "r"(half + 1), "r"(128) : "memory");
}

extern __shared__ float smem[];

__global__ __launch_bounds__(256, 1) void fused_attn_kernel(
    const float* __restrict__ obs,
    const float* __restrict__ W1, const float* __restrict__ b1,
    const float* __restrict__ W2, const float* __restrict__ b2,
    const float* __restrict__ W3, const float* __restrict__ b3,
    float* __restrict__ out)
{
    const int tid  = threadIdx.x;
    const int half = tid >> 7;     // 0 or 1: which batch row of the pair
    const int t    = tid & 127;    // output-dim lane, 0..127

    float* W2q = smem;                          // [128][132]
    float* W3q = smem + W_FLOATS;               // [128][132]
    float* hb  = smem + 2 * W_FLOATS + half * HALF_FLOATS;
    float* fs      = hb;                        // 512: raw att (32 objs x 16)
    float* bufA    = hb + 512;                  // [32][132]
    float* bufB    = bufA + kObj * kPad;        // [32][132]
    float* query_s = bufB + kObj * kPad;        // 128
    float* p_s     = query_s + kD;              // 128
    float* logit_s = p_s + kD;                  // 32
    float* w_s     = logit_s + kObj;            // 32

    // ---- stage W2 / W3 into padded smem (coalesced float4) ----
    for (int i = tid; i < (kD * kD) / 4; i += 256) {
        int r = i >> 5, c4 = i & 31;
        *(float4*)(W2q + r * kPad + c4 * 4) = ((const float4*)W2)[i];
        *(float4*)(W3q + r * kPad + c4 * 4) = ((const float4*)W3)[i];
    }
    // ---- per-thread W1 row + biases in registers ----
    float w1r[15];
    #pragma unroll
    for (int f = 0; f < 15; ++f) w1r[f] = W1[t * 15 + f];
    const float b1r = b1[t], b2r = b2[t], b3r = b3[t];
    __syncthreads();

    for (int pair = blockIdx.x; pair < kBatch / 2; pair += kSMs) {
        const int b = pair * 2 + half;
        const float*  orow   = obs + (size_t)b * kObs;
        float*        outrow = out + (size_t)b * kOutC;

        // ---- load att (512 floats) into fs; write aux passthrough ----
        *(float4*)(fs + 4 * t) = ((const float4*)(orow + 32))[t];
        if (t < 16) {
            float4 v = (t < 8) ? ((const float4*)orow)[t]
                               : ((const float4*)orow)[136 + (t - 8)];
            ((float4*)outrow)[t] = v;
        }
        half_bar(half);

        // ---- mask sum (all threads redundantly; broadcast LDS) ----
        float msum = 0.f;
        #pragma unroll
        for (int o = 0; o < kObj; ++o) msum += fs[o * 16 + 15];

        // ---- layer 1: h1[o][t] = relu(W1[t,:].f[o,:] + b1[t]) ----
        for (int o = 0; o < kObj; ++o) {
            const float4 f0 = *(const float4*)(fs + o * 16);
            const float4 f1 = *(const float4*)(fs + o * 16 + 4);
            const float4 f2 = *(const float4*)(fs + o * 16 + 8);
            const float4 f3 = *(const float4*)(fs + o * 16 + 12);
            float a = b1r;
            a += w1r[0] * f0.x + w1r[1] * f0.y + w1r[2]  * f0.z + w1r[3]  * f0.w;
            a += w1r[4] * f1.x + w1r[5] * f1.y + w1r[6]  * f1.z + w1r[7]  * f1.w;
            a += w1r[8] * f2.x + w1r[9] * f2.y + w1r[10] * f2.z + w1r[11] * f2.w;
            a += w1r[12] * f3.x + w1r[13] * f3.y + w1r[14] * f3.z;   // f3.w = mask, skipped
            bufA[o * kPad + t] = fmaxf(a, 0.f);
        }
        half_bar(half);

        // ---- layer 2: bufB = relu(W2 @ bufA + b2), 8-obj x 4-e blocking ----
        {
            const float* wrow = W2q + t * kPad;
            for (int g = 0; g < 4; ++g) {
                float acc[8];
                #pragma unroll
                for (int i = 0; i < 8; ++i) acc[i] = b2r;
                const float* hbase = bufA + g * 8 * kPad;
                #pragma unroll 8
                for (int e4 = 0; e4 < 32; ++e4) {
                    const float4 w = *(const float4*)(wrow + 4 * e4);
                    #pragma unroll
                    for (int o8 = 0; o8 < 8; ++o8) {
                        const float4 h = *(const float4*)(hbase + o8 * kPad + 4 * e4);
                        acc[o8] += w.x * h.x + w.y * h.y + w.z * h.z + w.w * h.w;
                    }
                }
                #pragma unroll
                for (int o8 = 0; o8 < 8; ++o8)
                    bufB[(g * 8 + o8) * kPad + t] = fmaxf(acc[o8], 0.f);
            }
        }
        half_bar(half);

        // ---- layer 3 + mask + query accumulation: bufA = xr ----
        float qsum = 0.f;
        {
            const float* wrow = W3q + t * kPad;
            for (int g = 0; g < 4; ++g) {
                float acc[8];
                #pragma unroll
                for (int i = 0; i < 8; ++i) acc[i] = b3r;
                const float* hbase = bufB + g * 8 * kPad;
                #pragma unroll 8
                for (int e4 = 0; e4 < 32; ++e4) {
                    const float4 w = *(const float4*)(wrow + 4 * e4);
                    #pragma unroll
                    for (int o8 = 0; o8 < 8; ++o8) {
                        const float4 h = *(const float4*)(hbase + o8 * kPad + 4 * e4);
                        acc[o8] += w.x * h.x + w.y * h.y + w.z * h.z + w.w * h.w;
                    }
                }
                #pragma unroll
                for (int o8 = 0; o8 < 8; ++o8) {
                    const int o = g * 8 + o8;
                    const float xr = acc[o8] * fs[o * 16 + 15];
                    bufA[o * kPad + t] = xr;
                    qsum += xr;
                }
            }
        }
        query_s[t] = qsum / (msum + 1e-5f);
        half_bar(half);

        // ---- p = M query  (M resident in L2) ----
        float p = 0.f;
        #pragma unroll 8
        for (int j = 0; j < kD; ++j)
            p += g_MT[j * kD + t] * query_s[j];
        p_s[t] = p;
        half_bar(half);

        // ---- logits: 4 threads per object, conflict-free smem pattern ----
        {
            const int o = t >> 2, c = t & 3;
            float ls = 0.f;
            #pragma unroll 8
            for (int k = 0; k < 32; ++k)
                ls += p_s[c + 4 * k] * bufA[o * kPad + c + 4 * k];
            ls += __shfl_xor_sync(0xffffffffu, ls, 1);
            ls += __shfl_xor_sync(0xffffffffu, ls, 2);
            if (c == 0)
                logit_s[o] = ls + (1.f - fs[o * 16 + 15]) * -1e9f;
        }
        half_bar(half);

        // ---- softmax over 32 objects (warp 0 of this half) ----
        if (t < 32) {
            const float l = logit_s[t];
            float mx = l;
            #pragma unroll
            for (int s = 16; s > 0; s >>= 1)
                mx = fmaxf(mx, __shfl_xor_sync(0xffffffffu, mx, s));
            const float e = __expf(l - mx);
            float ssum = e;
            #pragma unroll
            for (int s = 16; s > 0; s >>= 1)
                ssum += __shfl_xor_sync(0xffffffffu, ssum, s);
            w_s[t] = e / ssum;
        }
        half_bar(half);

        // ---- out_att = sum_o w[o] * xr[o] ----
        float oacc = 0.f;
        #pragma unroll 8
        for (int o = 0; o < kObj; ++o)
            oacc += w_s[o] * bufA[o * kPad + t];
        outrow[64 + t] = oacc;

        half_bar(half);   // protect fs/bufA before next iteration's overwrite
    }
}

extern "C" void kernel_launch(void* const* d_in, const int* in_sizes, int n_in,
                              void* d_out, int out_size) {
    const float* obs = (const float*)d_in[0];
    const float* W1  = (const float*)d_in[1];
    const float* b1  = (const float*)d_in[2];
    const float* W2  = (const float*)d_in[3];
    const float* b2  = (const float*)d_in[4];
    const float* W3  = (const float*)d_in[5];
    const float* b3  = (const float*)d_in[6];
    const float* Uq  = (const float*)d_in[7];
    const float* Ur  = (const float*)d_in[8];
    float* out = (float*)d_out;

    cudaFuncSetAttribute(fused_attn_kernel,
                         cudaFuncAttributeMaxDynamicSharedMemorySize,
                         (int)SMEM_BYTES);

    precompute_MT<<<kD, kD>>>(Uq, Ur);
    fused_attn_kernel<<<kSMs, 256, SMEM_BYTES>>>(obs, W1, b1, W2, b2, W3, b3, out);
}

// round 6
// speedup vs baseline: 3.6756x; 3.6710x over previous
#include <cuda_runtime.h>
#include <cuda_fp16.h>
#include <cstdint>

// ---------------------------------------------------------------------------
// BaseAttention fused kernel — HMMA (mma.sync.m16n8k16 f16->f32) version.
// Works on the harness's compute_100 PTX target (no sm_100a-only features).
//
// Per tile = 4 batch rows = 128 object rows (M=128), N=128, K={16,128,128}:
//   warp w owns rows [16w, 16w+16): GEMM strips via ldmatrix + mma.sync,
//   epilogue writes fp16 back into the A tile (warp-local -> no CTA sync).
// Attention tail in fp32 (g_MT = Ur^T Uq folded, fp32 in L2).
// ---------------------------------------------------------------------------

#define kBatch   32768
#define kTiles   (kBatch / 4)     // 8192
#define kGrid    148
#define kThreads 256

// smem byte offsets
#define OFF_FS    0                  // [4][512] f32 raw att        8192
#define OFF_BIAS  8192               // b1,b2,b3 f32                1536
#define OFF_Q     9728               // 4x128 f32                   2048
#define OFF_P     11776              // 4x128 f32                   2048
#define OFF_LG    13824              // 128 f32                      512
#define OFF_WS    14336              // 128 f32                      512
#define OFF_MS    14848              // 4 f32 (+pad)                  64
#define OFF_W1T   14912              // [128][24] f16 (k-pad 15->16) 6144
#define OFF_A     21056              // [128][136] f16 activations  34816
#define OFF_W2T   55872              // [128][136] f16              34816
#define OFF_W3T   90688              // [128][136] f16              34816
#define OFF_XR    125504             // [128][129] f32              66048
#define SMEM_BYTES 191552            // < 232448 opt-in limit

#define A_STRIDE  272                // bytes per A/W row (136 halves)
#define W1_STRIDE 48                 // bytes per W1 row (24 halves)

// packed fp16 weight images (exact smem layout)
__device__ __half g_W1h[128 * 24];
__device__ __half g_W2h[128 * 136];
__device__ __half g_W3h[128 * 136];
__device__ float  g_MT[128 * 128];   // MT[j*128+t] = sum_k Ur[k,t]*Uq[k,j]

__device__ __forceinline__ uint32_t smem_u32(const void* p) {
    uint32_t a;
    asm("{ .reg .u64 t; cvta.to.shared.u64 t, %1; cvt.u32.u64 %0, t; }" : "=r"(a) : "l"(p));
    return a;
}

#define LDSM_X4(R0,R1,R2,R3,ADDR) \
    asm volatile("ldmatrix.sync.aligned.m8n8.x4.shared.b16 {%0,%1,%2,%3}, [%4];" \
                 : "=r"(R0), "=r"(R1), "=r"(R2), "=r"(R3) : "r"(ADDR))

#define MMA_16816(D_, A0,A1,A2,A3, B0,B1) \
    asm volatile("mma.sync.aligned.m16n8k16.row.col.f32.f16.f16.f32 " \
                 "{%0,%1,%2,%3}, {%4,%5,%6,%7}, {%8,%9}, {%0,%1,%2,%3};" \
                 : "+f"((D_)[0]), "+f"((D_)[1]), "+f"((D_)[2]), "+f"((D_)[3]) \
                 : "r"(A0), "r"(A1), "r"(A2), "r"(A3), "r"(B0), "r"(B1))

// ---- prep kernels ----
__global__ void pack_weights(const float* __restrict__ W1,
                             const float* __restrict__ W2,
                             const float* __restrict__ W3) {
    int i = blockIdx.x * 256 + threadIdx.x;      // 68*256 = 17408
    if (i < 128 * 136) {
        int n = i / 136, c = i % 136;
        float v2 = (c < 128) ? W2[n * 128 + c] : 0.f;
        float v3 = (c < 128) ? W3[n * 128 + c] : 0.f;
        g_W2h[i] = __float2half(v2);
        g_W3h[i] = __float2half(v3);
    }
    if (i < 128 * 24) {
        int n = i / 24, c = i % 24;
        g_W1h[i] = __float2half((c < 15) ? W1[n * 15 + c] : 0.f);
    }
}

__global__ void precompute_MT(const float* __restrict__ Uq, const float* __restrict__ Ur) {
    int j = blockIdx.x, t = threadIdx.x;
    float acc = 0.f;
    #pragma unroll 8
    for (int k = 0; k < 128; ++k)
        acc += Ur[k * 128 + t] * Uq[k * 128 + j];
    g_MT[j * 128 + t] = acc;
}

// K-loop GEMM on one 16-row strip: D[16 rows][128 cols] += A_strip @ W^T
template<int NK, int BSTRIDE>
__device__ __forceinline__ void gemm_strip(uint32_t aAddr, uint32_t bAddr, float (&d)[16][4]) {
    #pragma unroll
    for (int k = 0; k < NK; ++k) {
        uint32_t a0, a1, a2, a3;
        LDSM_X4(a0, a1, a2, a3, aAddr + k * 32);
        #pragma unroll
        for (int nt2 = 0; nt2 < 8; ++nt2) {
            uint32_t q0, q1, q2, q3;
            LDSM_X4(q0, q1, q2, q3, bAddr + nt2 * 16 * BSTRIDE + k * 32);
            MMA_16816(d[2 * nt2],     a0, a1, a2, a3, q0, q1);
            MMA_16816(d[2 * nt2 + 1], a0, a1, a2, a3, q2, q3);
        }
    }
}

extern __shared__ char smem[];

__global__ __launch_bounds__(kThreads, 1) void fused_attn_hmma(
    const float* __restrict__ obs,
    const float* __restrict__ b1, const float* __restrict__ b2, const float* __restrict__ b3,
    float* __restrict__ out)
{
    const uint32_t sb = smem_u32(smem);
    const int tid = threadIdx.x;
    const int wid = tid >> 5, lane = tid & 31;
    const int r0  = wid * 16;                     // warp's strip base row

    // stage weights + biases
    {
        const uint4* s1 = (const uint4*)g_W1h;
        const uint4* s2 = (const uint4*)g_W2h;
        const uint4* s3 = (const uint4*)g_W3h;
        for (int i = tid; i < 384;  i += kThreads) *(uint4*)(smem + OFF_W1T + i * 16) = s1[i];
        for (int i = tid; i < 2176; i += kThreads) *(uint4*)(smem + OFF_W2T + i * 16) = s2[i];
        for (int i = tid; i < 2176; i += kThreads) *(uint4*)(smem + OFF_W3T + i * 16) = s3[i];
        if (tid < 128) {
            ((float*)(smem + OFF_BIAS))[tid]       = b1[tid];
            ((float*)(smem + OFF_BIAS))[128 + tid] = b2[tid];
            ((float*)(smem + OFF_BIAS))[256 + tid] = b3[tid];
        }
    }
    __syncthreads();

    float* fs   = (float*)(smem + OFF_FS);
    float* xr   = (float*)(smem + OFF_XR);
    const float* bias = (const float*)(smem + OFF_BIAS);
    float* q_s  = (float*)(smem + OFF_Q);
    float* p_s  = (float*)(smem + OFF_P);
    float* lg_s = (float*)(smem + OFF_LG);
    float* w_s  = (float*)(smem + OFF_WS);
    float* ms_s = (float*)(smem + OFF_MS);

    // ldmatrix lane addresses (tile-invariant)
    const uint32_t aAddr = sb + OFF_A + (uint32_t)(r0 + (lane & 15)) * A_STRIDE + (uint32_t)(lane >> 4) * 16;
    const uint32_t brow  = (uint32_t)((lane & 7) + ((lane >> 4) << 3));
    const uint32_t koff  = (uint32_t)(((lane >> 3) & 1) * 16);
    const uint32_t bW1   = sb + OFF_W1T + brow * W1_STRIDE + koff;
    const uint32_t bW2   = sb + OFF_W2T + brow * A_STRIDE + koff;
    const uint32_t bW3   = sb + OFF_W3T + brow * A_STRIDE + koff;

    // D-fragment / epilogue lane mapping
    const int rA = r0 + (lane >> 2);              // rows rA and rA+8
    const int cn = (lane & 3) * 2;                // col offset within n-tile

    for (int tile = blockIdx.x; tile < kTiles; tile += kGrid) {
        const int b0 = tile * 4;
        const float4* obs4 = (const float4*)(obs + (size_t)b0 * 576);
        float4*       out4 = (float4*)(out + (size_t)b0 * 192);

        // ---- stage raw att + aux passthrough ----
        for (int i = tid; i < 512; i += kThreads)
            ((float4*)fs)[i] = obs4[(i >> 7) * 144 + 8 + (i & 127)];
        if (tid < 64) {
            const int lb = tid >> 4, j = tid & 15;
            float4 v = (j < 8) ? obs4[lb * 144 + j] : obs4[lb * 144 + 136 + (j - 8)];
            out4[lb * 48 + j] = v;
        }
        __syncthreads();

        if (tid < 4) {                            // mask sums
            float s = 0.f;
            #pragma unroll
            for (int o = 0; o < 32; ++o) s += fs[tid * 512 + o * 16 + 15];
            ms_s[tid] = s;
        }

        // ---- A1: feats fp16 into A tile (warp-local rows) ----
        {
            const int rr = r0 + (lane & 15);
            const int ch = lane >> 4;
            const float* fr = fs + rr * 16 + ch * 8;
            #pragma unroll
            for (int j = 0; j < 4; ++j) {
                float x0 = fr[2 * j], x1 = fr[2 * j + 1];
                if (ch == 1 && j == 3) x1 = 0.f;  // col 15 = mask -> 0
                __half2 h = __floats2half2_rn(x0, x1);
                *(uint32_t*)(smem + OFF_A + rr * A_STRIDE + (ch * 8 + 2 * j) * 2) = *(uint32_t*)&h;
            }
        }
        __syncwarp();

        float d[16][4];

        // ---- layer 1 (K=16) ----
        #pragma unroll
        for (int nt = 0; nt < 16; ++nt)
            { d[nt][0] = d[nt][1] = d[nt][2] = d[nt][3] = 0.f; }
        gemm_strip<1, W1_STRIDE>(aAddr, bW1, d);
        #pragma unroll
        for (int nt = 0; nt < 16; ++nt) {         // epi: relu(+b1) -> A fp16
            const int n = nt * 8 + cn;
            __half2 h0 = __floats2half2_rn(fmaxf(d[nt][0] + bias[n],     0.f),
                                           fmaxf(d[nt][1] + bias[n + 1], 0.f));
            __half2 h1 = __floats2half2_rn(fmaxf(d[nt][2] + bias[n],     0.f),
                                           fmaxf(d[nt][3] + bias[n + 1], 0.f));
            *(uint32_t*)(smem + OFF_A + rA * A_STRIDE + n * 2)       = *(uint32_t*)&h0;
            *(uint32_t*)(smem + OFF_A + (rA + 8) * A_STRIDE + n * 2) = *(uint32_t*)&h1;
        }
        __syncwarp();

        // ---- layer 2 (K=128) ----
        #pragma unroll
        for (int nt = 0; nt < 16; ++nt)
            { d[nt][0] = d[nt][1] = d[nt][2] = d[nt][3] = 0.f; }
        gemm_strip<8, A_STRIDE>(aAddr, bW2, d);
        #pragma unroll
        for (int nt = 0; nt < 16; ++nt) {         // epi: relu(+b2) -> A fp16
            const int n = nt * 8 + cn;
            __half2 h0 = __floats2half2_rn(fmaxf(d[nt][0] + bias[128 + n],     0.f),
                                           fmaxf(d[nt][1] + bias[128 + n + 1], 0.f));
            __half2 h1 = __floats2half2_rn(fmaxf(d[nt][2] + bias[128 + n],     0.f),
                                           fmaxf(d[nt][3] + bias[128 + n + 1], 0.f));
            *(uint32_t*)(smem + OFF_A + rA * A_STRIDE + n * 2)       = *(uint32_t*)&h0;
            *(uint32_t*)(smem + OFF_A + (rA + 8) * A_STRIDE + n * 2) = *(uint32_t*)&h1;
        }
        __syncwarp();

        // ---- layer 3 (K=128) + mask -> xr fp32 ----
        #pragma unroll
        for (int nt = 0; nt < 16; ++nt)
            { d[nt][0] = d[nt][1] = d[nt][2] = d[nt][3] = 0.f; }
        gemm_strip<8, A_STRIDE>(aAddr, bW3, d);
        {
            const float mkA = fs[rA * 16 + 15];
            const float mkB = fs[(rA + 8) * 16 + 15];
            #pragma unroll
            for (int nt = 0; nt < 16; ++nt) {
                const int n = nt * 8 + cn;
                xr[rA * 129 + n]           = (d[nt][0] + bias[256 + n])     * mkA;
                xr[rA * 129 + n + 1]       = (d[nt][1] + bias[256 + n + 1]) * mkA;
                xr[(rA + 8) * 129 + n]     = (d[nt][2] + bias[256 + n])     * mkB;
                xr[(rA + 8) * 129 + n + 1] = (d[nt][3] + bias[256 + n + 1]) * mkB;
            }
        }
        __syncthreads();

        // ---- attention (fp32) ----
        const int lb2 = tid >> 7, dd = tid & 127;

        #pragma unroll
        for (int s2 = 0; s2 < 2; ++s2) {          // query
            const int lb = lb2 + 2 * s2;
            float s = 0.f;
            #pragma unroll 8
            for (int o = 0; o < 32; ++o) s += xr[(lb * 32 + o) * 129 + dd];
            q_s[lb * 128 + dd] = s / (ms_s[lb] + 1e-5f);
        }
        __syncthreads();

        {                                         // p = MT q (g_MT fp32 in L2)
            const int lb = tid >> 6, c4 = (tid & 63) * 4;
            float a0 = 0.f, a1 = 0.f, a2 = 0.f, a3 = 0.f;
            const float* qrow = q_s + lb * 128;
            #pragma unroll 4
            for (int j = 0; j < 128; ++j) {
                const float4 m = *(const float4*)(g_MT + j * 128 + c4);
                const float qv = qrow[j];
                a0 += m.x * qv; a1 += m.y * qv; a2 += m.z * qv; a3 += m.w * qv;
            }
            float4* pq = (float4*)(p_s + lb * 128 + c4);
            *pq = make_float4(a0, a1, a2, a3);
        }
        __syncthreads();

        {                                         // logits (2 threads / row)
            const int row = tid >> 1, c = tid & 1;
            const int lb = row >> 5;
            float ls = 0.f;
            #pragma unroll 8
            for (int k = 0; k < 64; ++k)
                ls += p_s[lb * 128 + c + 2 * k] * xr[row * 129 + c + 2 * k];
            ls += __shfl_xor_sync(0xffffffffu, ls, 1);
            if (c == 0)
                lg_s[row] = ls + (1.f - fs[row * 16 + 15]) * -1e9f;
        }
        __syncthreads();

        if (wid < 4) {                            // softmax (one warp / batch row)
            const float l = lg_s[wid * 32 + lane];
            float mx = l;
            #pragma unroll
            for (int s = 16; s > 0; s >>= 1) mx = fmaxf(mx, __shfl_xor_sync(0xffffffffu, mx, s));
            const float e = __expf(l - mx);
            float ss = e;
            #pragma unroll
            for (int s = 16; s > 0; s >>= 1) ss += __shfl_xor_sync(0xffffffffu, ss, s);
            w_s[wid * 32 + lane] = e / ss;
        }
        __syncthreads();

        #pragma unroll
        for (int s2 = 0; s2 < 2; ++s2) {          // out_att
            const int lb = lb2 + 2 * s2;
            float acc = 0.f;
            #pragma unroll 8
            for (int o = 0; o < 32; ++o)
                acc += w_s[lb * 32 + o] * xr[(lb * 32 + o) * 129 + dd];
            out[(size_t)(b0 + lb) * 192 + 64 + dd] = acc;
        }
        __syncthreads();                          // protect fs/xr for next tile
    }
}

extern "C" void kernel_launch(void* const* d_in, const int* in_sizes, int n_in,
                              void* d_out, int out_size) {
    const float* obs = (const float*)d_in[0];
    const float* W1  = (const float*)d_in[1];
    const float* b1  = (const float*)d_in[2];
    const float* W2  = (const float*)d_in[3];
    const float* b2  = (const float*)d_in[4];
    const float* W3  = (const float*)d_in[5];
    const float* b3  = (const float*)d_in[6];
    const float* Uq  = (const float*)d_in[7];
    const float* Ur  = (const float*)d_in[8];
    float* out = (float*)d_out;

    cudaFuncSetAttribute(fused_attn_hmma,
                         cudaFuncAttributeMaxDynamicSharedMemorySize, (int)SMEM_BYTES);

    pack_weights<<<68, 256>>>(W1, W2, W3);
    precompute_MT<<<128, 128>>>(Uq, Ur);
    fused_attn_hmma<<<kGrid, kThreads, SMEM_BYTES>>>(obs, b1, b2, b3, out);
}

// round 7
// speedup vs baseline: 6.0025x; 1.6330x over previous
#include <cuda_runtime.h>
#include <cuda_fp16.h>
#include <cstdint>

// ---------------------------------------------------------------------------
// BaseAttention fused kernel — HMMA (mma.sync.m16n8k16 f16->f32), 512 threads.
// Per tile = 4 batch rows = 128 object rows. 16 warps: warp (s, nh) owns the
// 16-row strip s and the 64-col N-half nh. Epilogues write fp16 back to the
// shared A tile; layers separated by __syncthreads.
// Attention tail fp32; p = (Ur^T Uq) q with 4x-deduplicated g_MT loads.
// ---------------------------------------------------------------------------

#define kBatch   32768
#define kTiles   (kBatch / 4)     // 8192
#define kGrid    148
#define kThreads 512

// smem byte offsets
#define OFF_FS    0                  // [4][512] f32 raw att        8192
#define OFF_BIAS  8192               // b1,b2,b3 f32                1536
#define OFF_Q     9728               // 4x128 f32                   2048
#define OFF_P     11776              // 4x128 f32                   2048
#define OFF_LG    13824              // 128 f32                      512
#define OFF_WS    14336              // 128 f32                      512
#define OFF_MS    14848              // 4 f32 (+pad)                  64
#define OFF_PPART 14912              // [4][4][128] f32 p partials  8192
#define OFF_W1T   23104              // [128][24] f16 (k-pad 15->16) 6144
#define OFF_A     29248              // [128][136] f16 activations  34816
#define OFF_W2T   64064              // [128][136] f16              34816
#define OFF_W3T   98880              // [128][136] f16              34816
#define OFF_XR    133696             // [128][129] f32              66048
#define SMEM_BYTES 199744            // < 232448 opt-in limit

#define A_STRIDE  272                // bytes per A/W row (136 halves)
#define W1_STRIDE 48                 // bytes per W1 row (24 halves)

// packed fp16 weight images (exact smem layout)
__device__ __half g_W1h[128 * 24];
__device__ __half g_W2h[128 * 136];
__device__ __half g_W3h[128 * 136];
__device__ float  g_MT[128 * 128];   // MT[j*128+t] = sum_k Ur[k,t]*Uq[k,j]

__device__ __forceinline__ uint32_t smem_u32(const void* p) {
    uint32_t a;
    asm("{ .reg .u64 t; cvta.to.shared.u64 t, %1; cvt.u32.u64 %0, t; }" : "=r"(a) : "l"(p));
    return a;
}

#define LDSM_X4(R0,R1,R2,R3,ADDR) \
    asm volatile("ldmatrix.sync.aligned.m8n8.x4.shared.b16 {%0,%1,%2,%3}, [%4];" \
                 : "=r"(R0), "=r"(R1), "=r"(R2), "=r"(R3) : "r"(ADDR))

#define MMA_16816(D_, A0,A1,A2,A3, B0,B1) \
    asm volatile("mma.sync.aligned.m16n8k16.row.col.f32.f16.f16.f32 " \
                 "{%0,%1,%2,%3}, {%4,%5,%6,%7}, {%8,%9}, {%0,%1,%2,%3};" \
                 : "+f"((D_)[0]), "+f"((D_)[1]), "+f"((D_)[2]), "+f"((D_)[3]) \
                 : "r"(A0), "r"(A1), "r"(A2), "r"(A3), "r"(B0), "r"(B1))

// ---- prep kernels ----
__global__ void pack_weights(const float* __restrict__ W1,
                             const float* __restrict__ W2,
                             const float* __restrict__ W3) {
    int i = blockIdx.x * 256 + threadIdx.x;      // 68*256 = 17408
    if (i < 128 * 136) {
        int n = i / 136, c = i % 136;
        float v2 = (c < 128) ? W2[n * 128 + c] : 0.f;
        float v3 = (c < 128) ? W3[n * 128 + c] : 0.f;
        g_W2h[i] = __float2half(v2);
        g_W3h[i] = __float2half(v3);
    }
    if (i < 128 * 24) {
        int n = i / 24, c = i % 24;
        g_W1h[i] = __float2half((c < 15) ? W1[n * 15 + c] : 0.f);
    }
}

__global__ void precompute_MT(const float* __restrict__ Uq, const float* __restrict__ Ur) {
    int j = blockIdx.x, t = threadIdx.x;
    float acc = 0.f;
    #pragma unroll 8
    for (int k = 0; k < 128; ++k)
        acc += Ur[k * 128 + t] * Uq[k * 128 + j];
    g_MT[j * 128 + t] = acc;
}

// K-loop GEMM: D[16 rows][64 cols] += A_strip @ W_half^T
template<int NK, int BSTRIDE>
__device__ __forceinline__ void gemm_strip(uint32_t aAddr, uint32_t bAddr, float (&d)[8][4]) {
    #pragma unroll
    for (int k = 0; k < NK; ++k) {
        uint32_t a0, a1, a2, a3;
        LDSM_X4(a0, a1, a2, a3, aAddr + k * 32);
        #pragma unroll
        for (int nt2 = 0; nt2 < 4; ++nt2) {
            uint32_t q0, q1, q2, q3;
            LDSM_X4(q0, q1, q2, q3, bAddr + nt2 * 16 * BSTRIDE + k * 32);
            MMA_16816(d[2 * nt2],     a0, a1, a2, a3, q0, q1);
            MMA_16816(d[2 * nt2 + 1], a0, a1, a2, a3, q2, q3);
        }
    }
}

extern __shared__ char smem[];

__global__ __launch_bounds__(kThreads, 1) void fused_attn_hmma(
    const float* __restrict__ obs,
    const float* __restrict__ b1, const float* __restrict__ b2, const float* __restrict__ b3,
    float* __restrict__ out)
{
    const uint32_t sb = smem_u32(smem);
    const int tid  = threadIdx.x;
    const int wid  = tid >> 5, lane = tid & 31;
    const int s    = wid >> 1;               // strip 0..7
    const int nh   = wid & 1;                // N-half 0..1
    const int r0   = s * 16;
    const int nbase = nh * 64;

    // stage weights + biases
    {
        const uint4* s1 = (const uint4*)g_W1h;
        const uint4* s2 = (const uint4*)g_W2h;
        const uint4* s3 = (const uint4*)g_W3h;
        for (int i = tid; i < 384;  i += kThreads) *(uint4*)(smem + OFF_W1T + i * 16) = s1[i];
        for (int i = tid; i < 2176; i += kThreads) *(uint4*)(smem + OFF_W2T + i * 16) = s2[i];
        for (int i = tid; i < 2176; i += kThreads) *(uint4*)(smem + OFF_W3T + i * 16) = s3[i];
        if (tid < 128) {
            ((float*)(smem + OFF_BIAS))[tid]       = b1[tid];
            ((float*)(smem + OFF_BIAS))[128 + tid] = b2[tid];
            ((float*)(smem + OFF_BIAS))[256 + tid] = b3[tid];
        }
    }
    __syncthreads();

    float* fs   = (float*)(smem + OFF_FS);
    float* xr   = (float*)(smem + OFF_XR);
    const float* bias = (const float*)(smem + OFF_BIAS);
    float* q_s  = (float*)(smem + OFF_Q);
    float* p_s  = (float*)(smem + OFF_P);
    float* lg_s = (float*)(smem + OFF_LG);
    float* w_s  = (float*)(smem + OFF_WS);
    float* ms_s = (float*)(smem + OFF_MS);
    float* pp_s = (float*)(smem + OFF_PPART);

    // ldmatrix lane addresses (tile-invariant)
    const uint32_t aAddr = sb + OFF_A + (uint32_t)(r0 + (lane & 15)) * A_STRIDE + (uint32_t)(lane >> 4) * 16;
    const uint32_t brow  = (uint32_t)((lane & 7) + ((lane >> 4) << 3));
    const uint32_t koff  = (uint32_t)(((lane >> 3) & 1) * 16);
    const uint32_t bW1   = sb + OFF_W1T + (nbase + brow) * W1_STRIDE + koff;
    const uint32_t bW2   = sb + OFF_W2T + (nbase + brow) * A_STRIDE + koff;
    const uint32_t bW3   = sb + OFF_W3T + (nbase + brow) * A_STRIDE + koff;

    // D-fragment / epilogue lane mapping
    const int rA = r0 + (lane >> 2);          // rows rA and rA+8
    const int cn = (lane & 3) * 2;            // col offset within n-tile

    // ---- initial prefetch (tile = blockIdx.x always < kTiles) ----
    float4 pf_att, pf_aux;
    {
        const float4* o4 = (const float4*)(obs + (size_t)blockIdx.x * 4 * 576);
        pf_att = o4[(tid >> 7) * 144 + 8 + (tid & 127)];
        if (tid < 64) {
            const int lb = tid >> 4, j = tid & 15;
            pf_aux = (j < 8) ? o4[lb * 144 + j] : o4[lb * 144 + 136 + (j - 8)];
        }
    }

    for (int tile = blockIdx.x; tile < kTiles; tile += kGrid) {
        const int b0 = tile * 4;
        float4* out4 = (float4*)(out + (size_t)b0 * 192);

        // ---- commit prefetched att + aux passthrough ----
        ((float4*)fs)[tid] = pf_att;
        if (tid < 64)
            out4[(tid >> 4) * 48 + (tid & 15)] = pf_aux;
        __syncthreads();

        if (tid < 4) {                        // mask sums
            float ssum = 0.f;
            #pragma unroll
            for (int o = 0; o < 32; ++o) ssum += fs[tid * 512 + o * 16 + 15];
            ms_s[tid] = ssum;
        }

        // ---- A1: feats fp16 into A tile (all threads) ----
        for (int i = tid; i < 1024; i += kThreads) {
            const int r = i >> 3, cp = i & 7;
            float2 v = *(const float2*)(fs + r * 16 + 2 * cp);
            if (cp == 7) v.y = 0.f;           // col 15 = mask -> 0
            __half2 h = __floats2half2_rn(v.x, v.y);
            *(uint32_t*)(smem + OFF_A + r * A_STRIDE + cp * 4) = *(uint32_t*)&h;
        }
        __syncthreads();

        float d[8][4];

        // ---- layer 1 (K=16) ----
        #pragma unroll
        for (int nt = 0; nt < 8; ++nt)
            { d[nt][0] = d[nt][1] = d[nt][2] = d[nt][3] = 0.f; }
        gemm_strip<1, W1_STRIDE>(aAddr, bW1, d);
        __syncthreads();                      // A1 reads done before overwrite
        #pragma unroll
        for (int nt = 0; nt < 8; ++nt) {      // epi: relu(+b1) -> A fp16
            const int n = nbase + nt * 8 + cn;
            __half2 h0 = __floats2half2_rn(fmaxf(d[nt][0] + bias[n],     0.f),
                                           fmaxf(d[nt][1] + bias[n + 1], 0.f));
            __half2 h1 = __floats2half2_rn(fmaxf(d[nt][2] + bias[n],     0.f),
                                           fmaxf(d[nt][3] + bias[n + 1], 0.f));
            *(uint32_t*)(smem + OFF_A + rA * A_STRIDE + n * 2)       = *(uint32_t*)&h0;
            *(uint32_t*)(smem + OFF_A + (rA + 8) * A_STRIDE + n * 2) = *(uint32_t*)&h1;
        }
        __syncthreads();

        // ---- layer 2 (K=128) ----
        #pragma unroll
        for (int nt = 0; nt < 8; ++nt)
            { d[nt][0] = d[nt][1] = d[nt][2] = d[nt][3] = 0.f; }
        gemm_strip<8, A_STRIDE>(aAddr, bW2, d);
        __syncthreads();
        #pragma unroll
        for (int nt = 0; nt < 8; ++nt) {      // epi: relu(+b2) -> A fp16
            const int n = nbase + nt * 8 + cn;
            __half2 h0 = __floats2half2_rn(fmaxf(d[nt][0] + bias[128 + n],     0.f),
                                           fmaxf(d[nt][1] + bias[128 + n + 1], 0.f));
            __half2 h1 = __floats2half2_rn(fmaxf(d[nt][2] + bias[128 + n],     0.f),
                                           fmaxf(d[nt][3] + bias[128 + n + 1], 0.f));
            *(uint32_t*)(smem + OFF_A + rA * A_STRIDE + n * 2)       = *(uint32_t*)&h0;
            *(uint32_t*)(smem + OFF_A + (rA + 8) * A_STRIDE + n * 2) = *(uint32_t*)&h1;
        }
        __syncthreads();

        // ---- layer 3 (K=128) + mask -> xr fp32 ----
        #pragma unroll
        for (int nt = 0; nt < 8; ++nt)
            { d[nt][0] = d[nt][1] = d[nt][2] = d[nt][3] = 0.f; }
        gemm_strip<8, A_STRIDE>(aAddr, bW3, d);
        {
            const float mkA = fs[rA * 16 + 15];
            const float mkB = fs[(rA + 8) * 16 + 15];
            #pragma unroll
            for (int nt = 0; nt < 8; ++nt) {
                const int n = nbase + nt * 8 + cn;
                xr[rA * 129 + n]           = (d[nt][0] + bias[256 + n])     * mkA;
                xr[rA * 129 + n + 1]       = (d[nt][1] + bias[256 + n + 1]) * mkA;
                xr[(rA + 8) * 129 + n]     = (d[nt][2] + bias[256 + n])     * mkB;
                xr[(rA + 8) * 129 + n + 1] = (d[nt][3] + bias[256 + n + 1]) * mkB;
            }
        }
        __syncthreads();

        // ---- prefetch next tile's obs while the attention tail runs ----
        {
            const int ntile = tile + kGrid;
            if (ntile < kTiles) {
                const float4* o4 = (const float4*)(obs + (size_t)ntile * 4 * 576);
                pf_att = o4[(tid >> 7) * 144 + 8 + (tid & 127)];
                if (tid < 64) {
                    const int lb = tid >> 4, j = tid & 15;
                    pf_aux = (j < 8) ? o4[lb * 144 + j] : o4[lb * 144 + 136 + (j - 8)];
                }
            }
        }

        // ---- attention (fp32) ----
        const int lb = tid >> 7, dd = tid & 127;

        {                                     // query
            float ssum = 0.f;
            #pragma unroll 8
            for (int o = 0; o < 32; ++o) ssum += xr[(lb * 32 + o) * 129 + dd];
            q_s[lb * 128 + dd] = ssum / (ms_s[lb] + 1e-5f);
        }
        __syncthreads();

        {                                     // p partials: g = j-quarter, shared MT loads
            const int g = tid >> 7;
            float a0 = 0.f, a1 = 0.f, a2 = 0.f, a3 = 0.f;
            #pragma unroll 8
            for (int jj = 0; jj < 32; ++jj) {
                const int j = g * 32 + jj;
                const float m = g_MT[j * 128 + dd];
                a0 += m * q_s[j];
                a1 += m * q_s[128 + j];
                a2 += m * q_s[256 + j];
                a3 += m * q_s[384 + j];
            }
            pp_s[g * 512 + dd]       = a0;
            pp_s[g * 512 + 128 + dd] = a1;
            pp_s[g * 512 + 256 + dd] = a2;
            pp_s[g * 512 + 384 + dd] = a3;
        }
        __syncthreads();

        p_s[lb * 128 + dd] = pp_s[lb * 128 + dd]        + pp_s[512 + lb * 128 + dd]
                           + pp_s[1024 + lb * 128 + dd] + pp_s[1536 + lb * 128 + dd];
        __syncthreads();

        {                                     // logits (4 threads / row)
            const int row = tid >> 2, c = tid & 3;
            const int rlb = row >> 5;
            float ls = 0.f;
            #pragma unroll 8
            for (int k = 0; k < 32; ++k)
                ls += p_s[rlb * 128 + c + 4 * k] * xr[row * 129 + c + 4 * k];
            ls += __shfl_xor_sync(0xffffffffu, ls, 1);
            ls += __shfl_xor_sync(0xffffffffu, ls, 2);
            if (c == 0)
                lg_s[row] = ls + (1.f - fs[row * 16 + 15]) * -1e9f;
        }
        __syncthreads();

        if (tid < 128) {                      // softmax (one warp / batch row)
            const float l = lg_s[tid];
            float mx = l;
            #pragma unroll
            for (int sh = 16; sh > 0; sh >>= 1) mx = fmaxf(mx, __shfl_xor_sync(0xffffffffu, mx, sh));
            const float e = __expf(l - mx);
            float ssum = e;
            #pragma unroll
            for (int sh = 16; sh > 0; sh >>= 1) ssum += __shfl_xor_sync(0xffffffffu, ssum, sh);
            w_s[tid] = e / ssum;
        }
        __syncthreads();

        {                                     // out_att
            float acc = 0.f;
            #pragma unroll 8
            for (int o = 0; o < 32; ++o)
                acc += w_s[lb * 32 + o] * xr[(lb * 32 + o) * 129 + dd];
            out[(size_t)(b0 + lb) * 192 + 64 + dd] = acc;
        }
        __syncthreads();                      // protect fs/xr for next tile
    }
}

extern "C" void kernel_launch(void* const* d_in, const int* in_sizes, int n_in,
                              void* d_out, int out_size) {
    const float* obs = (const float*)d_in[0];
    const float* W1  = (const float*)d_in[1];
    const float* b1  = (const float*)d_in[2];
    const float* W2  = (const float*)d_in[3];
    const float* b2  = (const float*)d_in[4];
    const float* W3  = (const float*)d_in[5];
    const float* b3  = (const float*)d_in[6];
    const float* Uq  = (const float*)d_in[7];
    const float* Ur  = (const float*)d_in[8];
    float* out = (float*)d_out;

    cudaFuncSetAttribute(fused_attn_hmma,
                         cudaFuncAttributeMaxDynamicSharedMemorySize, (int)SMEM_BYTES);

    pack_weights<<<68, 256>>>(W1, W2, W3);
    precompute_MT<<<128, 128>>>(Uq, Ur);
    fused_attn_hmma<<<kGrid, kThreads, SMEM_BYTES>>>(obs, b1, b2, b3, out);
}